// round 2
// baseline (speedup 1.0000x reference)
#include <cuda_runtime.h>
#include <stdint.h>

// Problem shape (fixed by reference setup_inputs)
#define BB 16
#define TT 2048
#define DD 1024

// Scratch (no cudaMalloc allowed)
__device__ int g_mode;           // 0 = 1-byte bool, 1 = int32, 2 = int64
__device__ int g_order[BB * TT]; // source timestep for each compacted slot
__device__ int g_count[BB];      // valid rows per batch

// ---------------------------------------------------------------------------
// Kernel 1: detect mask storage format.
// Reads only the first B*T bytes (valid for every candidate layout).
//   1-byte bool : arbitrary nonzero bytes at any index
//   int32 0/1 LE: nonzero only at idx%4==0
//   int64 0/1 LE: nonzero only at idx%8==0
// ---------------------------------------------------------------------------
__global__ void detect_kernel(const uint8_t* __restrict__ m) {
    __shared__ int s_b123, s_b4;
    if (threadIdx.x == 0) { s_b123 = 0; s_b4 = 0; }
    __syncthreads();
    int a1 = 0, a2 = 0;
    for (int i = threadIdx.x; i < BB * TT; i += blockDim.x) {
        uint8_t v = m[i];
        if (v) {
            if (i & 3) a1 = 1;
            if ((i & 7) == 4) a2 = 1;
        }
    }
    if (a1) atomicOr(&s_b123, 1);
    if (a2) atomicOr(&s_b4, 1);
    __syncthreads();
    if (threadIdx.x == 0) g_mode = s_b123 ? 0 : (s_b4 ? 1 : 2);
}

__device__ __forceinline__ bool read_mask(const void* m, int i, int mode) {
    if (mode == 0) return ((const uint8_t*)m)[i] != 0;
    if (mode == 1) return ((const int*)m)[i] != 0;
    return ((const long long*)m)[i] != 0;
}

// ---------------------------------------------------------------------------
// Kernel 2: per-batch-row warp compaction scan.
// One warp per batch row; 64 ballot rounds over T=2048.
// ---------------------------------------------------------------------------
__global__ void scan_kernel(const void* __restrict__ mask,
                            float* __restrict__ out_counts) {
    const int b = blockIdx.x;
    const int lane = threadIdx.x;
    const int mode = g_mode;
    int base = 0;
#pragma unroll 4
    for (int c = 0; c < TT / 32; c++) {
        const int t = c * 32 + lane;
        const bool mv = read_mask(mask, b * TT + t, mode);
        const unsigned ball = __ballot_sync(0xffffffffu, mv);
        if (mv) {
            const int pos = base + __popc(ball & ((1u << lane) - 1u));
            g_order[b * TT + pos] = t;
        }
        base += __popc(ball);
    }
    if (lane == 0) {
        g_count[b] = base;
        out_counts[b] = (float)base;
    }
}

// ---------------------------------------------------------------------------
// Kernel 3: row gather. One block per output row (B*T blocks).
// 256 threads x float4 = 4 KB row, fully coalesced.
// ---------------------------------------------------------------------------
__global__ void __launch_bounds__(256)
copy_kernel(const float4* __restrict__ in,
            float4* __restrict__ out_collected,
            float* __restrict__ out_vidx) {
    const int row = blockIdx.x;          // b * TT + j
    const int b = row >> 11;             // / TT
    const int j = row & (TT - 1);
    const int cnt = g_count[b];
    float4* dst = out_collected + (size_t)row * (DD / 4);
    if (j < cnt) {
        const int src = g_order[row];
        const float4* s = in + ((size_t)(b * TT) + src) * (DD / 4);
        dst[threadIdx.x] = s[threadIdx.x];
        if (threadIdx.x == 0) out_vidx[row] = (float)src;
    } else {
        dst[threadIdx.x] = make_float4(0.f, 0.f, 0.f, 0.f);
        if (threadIdx.x == 0) out_vidx[row] = -1.0f;
    }
}

// ---------------------------------------------------------------------------
extern "C" void kernel_launch(void* const* d_in, const int* in_sizes, int n_in,
                              void* d_out, int out_size) {
    const float* inputs = (const float*)d_in[0];   // [B, T, D] fp32
    const void* mask = d_in[1];                    // [B, T] bool (layout detected)

    float* out = (float*)d_out;
    float* out_collected = out;                          // B*T*D
    float* out_vidx = out + (size_t)BB * TT * DD;        // B*T
    float* out_counts = out_vidx + (size_t)BB * TT;      // B

    detect_kernel<<<1, 1024>>>((const uint8_t*)mask);
    scan_kernel<<<BB, 32>>>(mask, out_counts);
    copy_kernel<<<BB * TT, 256>>>((const float4*)inputs,
                                  (float4*)out_collected, out_vidx);
}

// round 4
// speedup vs baseline: 1.1885x; 1.1885x over previous
#include <cuda_runtime.h>
#include <stdint.h>

// Problem shape (fixed by reference setup_inputs)
#define BB 16
#define TT 2048
#define DD 1024

// Scratch (no cudaMalloc allowed)
__device__ int g_order[BB * TT]; // source timestep for each compacted slot
__device__ int g_count[BB];      // valid rows per batch

__device__ __forceinline__ bool read_mask(const void* m, int i, int mode) {
    if (mode == 0) return ((const uint8_t*)m)[i] != 0;
    if (mode == 1) return ((const int*)m)[i] != 0;
    return ((const long long*)m)[i] != 0;
}

// ---------------------------------------------------------------------------
// Kernel 1: per-batch-row warp compaction scan, with inline mask-layout
// detection. One warp per batch row (16 blocks x 32 threads).
//
// Layout detection (redundant per block, first 2048 bytes, L2-resident):
//   1-byte bool : nonzero bytes appear at idx%4 != 0
//   int32 0/1 LE: nonzero bytes only at idx%4==0 (some at idx%8==4)
//   int64 0/1 LE: nonzero bytes only at idx%8==0
// Random ~50% mask density makes this classification unambiguous within
// the first 2048 bytes for all three layouts.
// ---------------------------------------------------------------------------
__global__ void scan_kernel(const void* __restrict__ mask,
                            float* __restrict__ out_counts) {
    const int b = blockIdx.x;
    const int lane = threadIdx.x;

    // --- mode detection: lane inspects bytes [lane*64, lane*64+64) ---
    const uint8_t* mb = (const uint8_t*)mask;
    int f123 = 0, f4 = 0;
#pragma unroll
    for (int k = 0; k < 64; k++) {
        const int i = lane * 64 + k;
        const uint8_t v = mb[i];
        if (v) {
            if (i & 3) f123 = 1;
            if ((i & 7) == 4) f4 = 1;
        }
    }
    const unsigned any123 = __ballot_sync(0xffffffffu, f123);
    const unsigned any4   = __ballot_sync(0xffffffffu, f4);
    const int mode = any123 ? 0 : (any4 ? 1 : 2);

    // --- load 64 mask values per lane into a 64-bit bitmap (parallel MLP) ---
    const int base_t = lane * 64;
    uint64_t bits = 0;
#pragma unroll
    for (int k = 0; k < 64; k++) {
        if (read_mask(mask, b * TT + base_t + k, mode))
            bits |= 1ull << k;
    }
    const int cnt = __popcll(bits);

    // --- inclusive warp prefix sum of per-lane counts ---
    int pre = cnt;
#pragma unroll
    for (int d = 1; d < 32; d <<= 1) {
        const int n = __shfl_up_sync(0xffffffffu, pre, d);
        if (lane >= d) pre += n;
    }
    const int total = __shfl_sync(0xffffffffu, pre, 31);
    int pos = pre - cnt;  // exclusive prefix = this lane's output base

    // --- emit indices: contiguous chunk per lane ---
    uint64_t r = bits;
    while (r) {
        const int k = __ffsll(r) - 1;
        g_order[b * TT + pos] = base_t + k;
        pos++;
        r &= r - 1;
    }

    if (lane == 31) {
        g_count[b] = total;
        out_counts[b] = (float)total;
    }
}

// ---------------------------------------------------------------------------
// Kernel 2: row gather. One block per output row (B*T blocks).
// 256 threads x float4 = 4 KB row, fully coalesced, streaming cache hints
// (192 MB stream >> 126 MB L2 -> evict-first avoids thrash).
// ---------------------------------------------------------------------------
__global__ void __launch_bounds__(256)
copy_kernel(const float4* __restrict__ in,
            float4* __restrict__ out_collected,
            float* __restrict__ out_vidx) {
    const int row = blockIdx.x;          // b * TT + j
    const int b = row >> 11;             // / TT
    const int j = row & (TT - 1);
    const int cnt = g_count[b];
    float4* dst = out_collected + (size_t)row * (DD / 4);
    if (j < cnt) {
        const int src = g_order[row];
        const float4* s = in + ((size_t)(b * TT) + src) * (DD / 4);
        const float4 v = __ldcs(s + threadIdx.x);
        __stcs(dst + threadIdx.x, v);
        if (threadIdx.x == 0) out_vidx[row] = (float)src;
    } else {
        __stcs(dst + threadIdx.x, make_float4(0.f, 0.f, 0.f, 0.f));
        if (threadIdx.x == 0) out_vidx[row] = -1.0f;
    }
}

// ---------------------------------------------------------------------------
extern "C" void kernel_launch(void* const* d_in, const int* in_sizes, int n_in,
                              void* d_out, int out_size) {
    const float* inputs = (const float*)d_in[0];   // [B, T, D] fp32
    const void* mask = d_in[1];                    // [B, T] bool (layout detected)

    float* out = (float*)d_out;
    float* out_collected = out;                          // B*T*D
    float* out_vidx = out + (size_t)BB * TT * DD;        // B*T
    float* out_counts = out_vidx + (size_t)BB * TT;      // B

    scan_kernel<<<BB, 32>>>(mask, out_counts);
    copy_kernel<<<BB * TT, 256>>>((const float4*)inputs,
                                  (float4*)out_collected, out_vidx);
}

// round 5
// speedup vs baseline: 1.4572x; 1.2260x over previous
#include <cuda_runtime.h>
#include <stdint.h>

#define BB 16
#define TT 2048
#define DD 1024
#define ROWS_PER_BLK 4

__device__ int g_order[BB * TT];
__device__ int g_count[BB];

__device__ __forceinline__ bool read_mask(const void* m, int i, int mode) {
    if (mode == 0) return ((const uint8_t*)m)[i] != 0;
    if (mode == 1) return ((const int*)m)[i] != 0;
    return ((const long long*)m)[i] != 0;
}

// ---------------------------------------------------------------------------
// Kernel 1: compaction scan. 16 blocks x 256 threads (8 warps / batch row).
// Inline mask-layout detection (1-byte bool / int32 / int64), redundant per
// block over the first 2048 mask bytes (L2-resident after first block).
// Each lane owns 8 contiguous timesteps -> 8-bit bitmap; warp prefix over
// lane counts; block prefix over warp totals via shared.
// ---------------------------------------------------------------------------
__global__ void __launch_bounds__(256)
scan_kernel(const void* __restrict__ mask, float* __restrict__ out_counts) {
    const int b = blockIdx.x;
    const int tid = threadIdx.x;
    const int warp = tid >> 5;
    const int lane = tid & 31;

    __shared__ int s_flags[2];     // [0]=idx%4!=0 nonzero, [1]=idx%8==4 nonzero
    __shared__ int s_wtot[8];
    if (tid < 2) s_flags[tid] = 0;
    __syncthreads();

    // --- mode detection: thread inspects bytes [tid*8, tid*8+8) ---
    {
        const uint8_t* mb = (const uint8_t*)mask;
        int f123 = 0, f4 = 0;
#pragma unroll
        for (int k = 0; k < 8; k++) {
            const int i = tid * 8 + k;
            if (mb[i]) { if (i & 3) f123 = 1; if ((i & 7) == 4) f4 = 1; }
        }
        if (f123) atomicOr(&s_flags[0], 1);
        if (f4)   atomicOr(&s_flags[1], 1);
    }
    __syncthreads();
    const int mode = s_flags[0] ? 0 : (s_flags[1] ? 1 : 2);

    // --- bitmap: lane owns timesteps [base_t, base_t+8) ---
    const int base_t = tid * 8;                 // tid in [0,256) -> covers TT
    unsigned bits = 0;
#pragma unroll
    for (int k = 0; k < 8; k++)
        if (read_mask(mask, b * TT + base_t + k, mode)) bits |= 1u << k;
    const int cnt = __popc(bits);

    // --- warp inclusive prefix of counts ---
    int pre = cnt;
#pragma unroll
    for (int d = 1; d < 32; d <<= 1) {
        const int n = __shfl_up_sync(0xffffffffu, pre, d);
        if (lane >= d) pre += n;
    }
    if (lane == 31) s_wtot[warp] = pre;
    __syncthreads();

    int wbase = 0;
#pragma unroll
    for (int w = 0; w < 8; w++) if (w < warp) wbase += s_wtot[w];
    int pos = wbase + pre - cnt;                // exclusive prefix

    // --- emit indices ---
    unsigned r = bits;
    while (r) {
        const int k = __ffs(r) - 1;
        g_order[b * TT + pos] = base_t + k;
        pos++;
        r &= r - 1;
    }

    if (tid == 255) {
        const int total = wbase + pre;
        g_count[b] = total;
        out_counts[b] = (float)total;
    }
}

// ---------------------------------------------------------------------------
// Kernel 2: row gather. 4 rows per block, 256 threads, 4 independent
// float4 load/store pairs per thread (MLP=4). Streaming hints: 192 MB
// stream exceeds the 126 MB L2.
// ---------------------------------------------------------------------------
__global__ void __launch_bounds__(256)
copy_kernel(const float4* __restrict__ in,
            float4* __restrict__ out_collected,
            float* __restrict__ out_vidx) {
    const int row0 = blockIdx.x * ROWS_PER_BLK;
    const int b = row0 >> 11;                   // 4 rows never cross a batch
    const int cnt = g_count[b];
    const int t = threadIdx.x;

    int src[ROWS_PER_BLK];
#pragma unroll
    for (int i = 0; i < ROWS_PER_BLK; i++) {
        const int row = row0 + i;
        const int j = row & (TT - 1);
        src[i] = (j < cnt) ? __ldg(&g_order[row]) : -1;
    }

    float4 v[ROWS_PER_BLK];
#pragma unroll
    for (int i = 0; i < ROWS_PER_BLK; i++) {
        v[i] = (src[i] >= 0)
             ? __ldcs(in + ((size_t)(b * TT) + src[i]) * (DD / 4) + t)
             : make_float4(0.f, 0.f, 0.f, 0.f);
    }
#pragma unroll
    for (int i = 0; i < ROWS_PER_BLK; i++)
        __stcs(out_collected + (size_t)(row0 + i) * (DD / 4) + t, v[i]);

    if (t == 0) {
#pragma unroll
        for (int i = 0; i < ROWS_PER_BLK; i++)
            out_vidx[row0 + i] = (float)src[i];
    }
}

// ---------------------------------------------------------------------------
extern "C" void kernel_launch(void* const* d_in, const int* in_sizes, int n_in,
                              void* d_out, int out_size) {
    const float* inputs = (const float*)d_in[0];   // [B, T, D] fp32
    const void* mask = d_in[1];                    // [B, T] bool

    float* out = (float*)d_out;
    float* out_collected = out;                          // B*T*D
    float* out_vidx = out + (size_t)BB * TT * DD;        // B*T
    float* out_counts = out_vidx + (size_t)BB * TT;      // B

    scan_kernel<<<BB, 256>>>(mask, out_counts);
    copy_kernel<<<(BB * TT) / ROWS_PER_BLK, 256>>>((const float4*)inputs,
                                                   (float4*)out_collected,
                                                   out_vidx);
}

// round 7
// speedup vs baseline: 1.4584x; 1.0009x over previous
#include <cuda_runtime.h>
#include <stdint.h>

#define BB 16
#define TT 2048
#define DD 1024
#define ROWS 8            // output rows per block
#define BLKS ((BB * TT) / ROWS)   // 4096

// ---------------------------------------------------------------------------
// Single fused kernel: each block
//   1. detects mask storage layout (bool8 / int32 / int64) from the first
//      2048 mask bytes (L2-resident, one uint64 per thread)
//   2. redundantly computes the compaction prefix for its batch row
//      (256 threads x 8 timesteps -> 8-bit bitmap -> warp+block prefix)
//   3. resolves the <=8 source indices this block needs (bit-picking)
//   4. gathers 8 rows of 4KB (two waves of 4 float4/thread, MLP=4),
//      streaming hints since the 192MB stream exceeds the 126MB L2
// ---------------------------------------------------------------------------
__global__ void __launch_bounds__(256)
fused_kernel(const float4* __restrict__ in,
             const void* __restrict__ mask,
             float4* __restrict__ out_collected,
             float* __restrict__ out_vidx,
             float* __restrict__ out_counts) {
    const int row0 = blockIdx.x * ROWS;
    const int b = row0 >> 11;            // ROWS divides TT; no batch crossing
    const int j0 = row0 & (TT - 1);
    const int t = threadIdx.x;
    const int warp = t >> 5;
    const int lane = t & 31;

    __shared__ int s_flags[2];
    __shared__ int s_wtot[8];
    __shared__ int s_total;
    __shared__ int s_src[ROWS];

    if (t < 2) s_flags[t] = 0;
    if (t < ROWS) s_src[t] = -1;
    __syncthreads();

    // --- 1. layout detection from first 2048 mask bytes ---
    {
        const unsigned long long det =
            ((const unsigned long long*)mask)[t];          // bytes [8t, 8t+8)
        // bytes 1,2,3,5,6,7 nonzero => 1-byte bool; byte 4 nonzero => int32
        if (det & 0xffffff00ffffff00ULL) atomicOr(&s_flags[0], 1);
        if (det & 0x000000ff00000000ULL) atomicOr(&s_flags[1], 1);
    }
    __syncthreads();
    const int mode = s_flags[0] ? 0 : (s_flags[1] ? 1 : 2);

    // --- 2. bitmap over this thread's 8 timesteps [8t, 8t+8) of batch b ---
    unsigned bits = 0;
    if (mode == 0) {
        const unsigned long long m =
            ((const unsigned long long*)mask)[b * 256 + t];
#pragma unroll
        for (int k = 0; k < 8; k++)
            if ((m >> (8 * k)) & 0xff) bits |= 1u << k;
    } else if (mode == 1) {
        const uint4* p = (const uint4*)mask + (size_t)b * 512 + t * 2;
        const uint4 a = p[0], c = p[1];
        if (a.x) bits |= 1u;  if (a.y) bits |= 2u;
        if (a.z) bits |= 4u;  if (a.w) bits |= 8u;
        if (c.x) bits |= 16u; if (c.y) bits |= 32u;
        if (c.z) bits |= 64u; if (c.w) bits |= 128u;
    } else {
        const ulonglong2* p = (const ulonglong2*)mask + (size_t)b * 1024 + t * 4;
#pragma unroll
        for (int q = 0; q < 4; q++) {
            const ulonglong2 a = p[q];
            if (a.x) bits |= 1u << (2 * q);
            if (a.y) bits |= 1u << (2 * q + 1);
        }
    }
    const int cnt = __popc(bits);

    // --- warp + block prefix ---
    int pre = cnt;
#pragma unroll
    for (int d = 1; d < 32; d <<= 1) {
        const int n = __shfl_up_sync(0xffffffffu, pre, d);
        if (lane >= d) pre += n;
    }
    if (lane == 31) s_wtot[warp] = pre;
    __syncthreads();
    int wbase = 0;
#pragma unroll
    for (int w = 0; w < 8; w++) if (w < warp) wbase += s_wtot[w];
    const int pos0 = wbase + pre - cnt;   // exclusive prefix for this thread
    if (t == 255) s_total = wbase + pre;

    // --- 3. resolve source indices for output positions j0..j0+ROWS-1 ---
#pragma unroll
    for (int i = 0; i < ROWS; i++) {
        const int j = j0 + i;
        if (j >= pos0 && j < pos0 + cnt) {
            unsigned r = bits;
            for (int need = j - pos0; need > 0; need--) r &= r - 1;
            s_src[i] = t * 8 + (__ffs(r) - 1);
        }
    }
    __syncthreads();

    // --- 4. gather 8 rows, two waves of 4 (MLP=4 each) ---
    const float4* in_b = in + (size_t)(b * TT) * (DD / 4);
#pragma unroll
    for (int half = 0; half < 2; half++) {
        int src[4];
        float4 v[4];
#pragma unroll
        for (int i = 0; i < 4; i++) src[i] = s_src[half * 4 + i];
#pragma unroll
        for (int i = 0; i < 4; i++)
            v[i] = (src[i] >= 0) ? __ldcs(in_b + (size_t)src[i] * (DD / 4) + t)
                                 : make_float4(0.f, 0.f, 0.f, 0.f);
#pragma unroll
        for (int i = 0; i < 4; i++)
            __stcs(out_collected +
                   (size_t)(row0 + half * 4 + i) * (DD / 4) + t, v[i]);
    }

    if (t < ROWS) out_vidx[row0 + t] = (float)s_src[t];
    if (j0 == 0 && t == 0) out_counts[b] = (float)s_total;
}

// ---------------------------------------------------------------------------
extern "C" void kernel_launch(void* const* d_in, const int* in_sizes, int n_in,
                              void* d_out, int out_size) {
    const float* inputs = (const float*)d_in[0];   // [B, T, D] fp32
    const void* mask = d_in[1];                    // [B, T] bool

    float* out = (float*)d_out;
    float* out_collected = out;                          // B*T*D
    float* out_vidx = out + (size_t)BB * TT * DD;        // B*T
    float* out_counts = out_vidx + (size_t)BB * TT;      // B

    fused_kernel<<<BLKS, 256>>>((const float4*)inputs, mask,
                                (float4*)out_collected, out_vidx, out_counts);
}